// round 2
// baseline (speedup 1.0000x reference)
#include <cuda_runtime.h>
#include <cuda_bf16.h>
#include <cstdint>

// ---------------------------------------------------------------------------
// Arch gate: tcgen05 is sm_103a-ONLY. The harness also builds a plain
// compute_103 PTX phase; guard all tcgen05 code so that phase compiles.
// The driver always selects the exact sm_103a cubin at runtime.
// ---------------------------------------------------------------------------
#if defined(__CUDA_ARCH__) && (__CUDA_ARCH__ == 1030) && defined(__CUDA_ARCH_FEAT_SM103_ALL)
#define TC_OK 1
#else
#define TC_OK 0
#endif

// ---------------------------------------------------------------------------
// Problem constants
// ---------------------------------------------------------------------------
#define N_EXPERTS 30
#define IN_SZ     1024
#define HID       2048
#define BATCH_SZ  8192

// ---------------------------------------------------------------------------
// Device scratch (static __device__ arrays: the sanctioned scratch mechanism)
// ---------------------------------------------------------------------------
__device__ __align__(16) __nv_bfloat16 g_xb [(size_t)BATCH_SZ * IN_SZ];          // 16 MB
__device__ __align__(16) __nv_bfloat16 g_w1b[(size_t)N_EXPERTS * HID * IN_SZ];   // 126 MB, [E][H][K] K-major
__device__ float g_zbuf[(size_t)N_EXPERTS * BATCH_SZ];                            // 1 MB

// ---------------------------------------------------------------------------
// PTX helpers
// ---------------------------------------------------------------------------
__device__ __forceinline__ uint32_t smem_to_u32(const void* p) {
    uint32_t a;
    asm("{ .reg .u64 t; cvta.to.shared.u64 t, %1; cvt.u32.u64 %0, t; }"
        : "=r"(a) : "l"(p));
    return a;
}

__device__ __forceinline__ uint32_t elect_one_pred() {
    uint32_t pred;
    asm volatile(
        "{\n\t.reg .pred p;\n\telect.sync _|p, 0xFFFFFFFF;\n\tselp.b32 %0, 1, 0, p;\n\t}"
        : "=r"(pred));
    return pred;
}

#define MBARRIER_INIT(addr, cnt) \
    asm volatile("mbarrier.init.shared.b64 [%0], %1;" :: "r"((uint32_t)(addr)), "r"((uint32_t)(cnt)) : "memory")

#define MBARRIER_WAIT_PARITY(mbar_smem_addr, phase_parity) do { \
    uint32_t _mbar = (uint32_t)(mbar_smem_addr); \
    uint32_t _parity = (uint32_t)(phase_parity); \
    uint32_t _done; \
    asm volatile( \
        "{\n\t.reg .pred p;\n\t" \
        "mbarrier.try_wait.parity.acquire.cta.shared::cta.b64 p, [%1], %2;\n\t" \
        "selp.b32 %0, 1, 0, p;\n\t}" \
        : "=r"(_done) : "r"(_mbar), "r"(_parity) : "memory"); \
    if (!_done) { \
        asm volatile( \
            "{\n\t.reg .pred P1;\n\t" \
            "WAIT_LOOP_%=:\n\t" \
            "mbarrier.try_wait.parity.acquire.cta.shared::cta.b64 P1, [%0], %1, 0x989680;\n\t" \
            "@P1 bra.uni WAIT_DONE_%=;\n\t" \
            "bra.uni WAIT_LOOP_%=;\n\t" \
            "WAIT_DONE_%=:\n\t}" \
            :: "r"(_mbar), "r"(_parity) : "memory"); \
    } \
} while (0)

__device__ __forceinline__ void cp16(uint32_t dst_smem, const void* src_gmem) {
    asm volatile("cp.async.cg.shared.global [%0], [%1], 16;"
                 :: "r"(dst_smem), "l"(src_gmem) : "memory");
}
__device__ __forceinline__ void cp_commit() { asm volatile("cp.async.commit_group;" ::: "memory"); }
__device__ __forceinline__ void cp_wait_1() { asm volatile("cp.async.wait_group 1;" ::: "memory"); }
__device__ __forceinline__ void cp_wait_0() { asm volatile("cp.async.wait_group 0;" ::: "memory"); }

#if TC_OK
#define TCGEN05_ALLOC(smem_result_addr, nCols) \
    asm volatile("tcgen05.alloc.cta_group::1.sync.aligned.shared::cta.b32 [%0], %1;" \
        :: "r"((uint32_t)(smem_result_addr)), "r"((uint32_t)(nCols)) : "memory")

#define TCGEN05_DEALLOC(tmem_addr, nCols) \
    asm volatile("tcgen05.dealloc.cta_group::1.sync.aligned.b32 %0, %1;" \
        :: "r"(tmem_addr), "r"((uint32_t)(nCols)))

#define TCGEN05_RELINQUISH_ALLOC_PERMIT() \
    asm volatile("tcgen05.relinquish_alloc_permit.cta_group::1.sync.aligned;")

#define TCGEN05_COMMIT(mbar_smem_addr) \
    asm volatile("tcgen05.commit.cta_group::1.mbarrier::arrive::one.shared::cluster.b64 [%0];" \
        :: "r"((uint32_t)(mbar_smem_addr)) : "memory")

#define TCGEN05_WAIT_LD()  asm volatile("tcgen05.wait::ld.sync.aligned;" ::: "memory")
#define TCGEN05_FENCE_BEFORE() asm volatile("tcgen05.fence::before_thread_sync;" ::: "memory")
#define TCGEN05_FENCE_AFTER()  asm volatile("tcgen05.fence::after_thread_sync;" ::: "memory")
#define FENCE_PROXY_ASYNC_SHARED_CTA() asm volatile("fence.proxy.async.shared::cta;" ::: "memory")

#define TCGEN05_LD_32X32B_X32(r, tmem_addr) \
    asm volatile( \
        "tcgen05.ld.sync.aligned.32x32b.x32.b32 " \
        "{%0, %1, %2, %3, %4, %5, %6, %7, " \
        " %8, %9, %10, %11, %12, %13, %14, %15, " \
        " %16, %17, %18, %19, %20, %21, %22, %23, " \
        " %24, %25, %26, %27, %28, %29, %30, %31}, [%32];" \
        : "=r"((r)[0]),  "=r"((r)[1]),  "=r"((r)[2]),  "=r"((r)[3]), \
          "=r"((r)[4]),  "=r"((r)[5]),  "=r"((r)[6]),  "=r"((r)[7]), \
          "=r"((r)[8]),  "=r"((r)[9]),  "=r"((r)[10]), "=r"((r)[11]), \
          "=r"((r)[12]), "=r"((r)[13]), "=r"((r)[14]), "=r"((r)[15]), \
          "=r"((r)[16]), "=r"((r)[17]), "=r"((r)[18]), "=r"((r)[19]), \
          "=r"((r)[20]), "=r"((r)[21]), "=r"((r)[22]), "=r"((r)[23]), \
          "=r"((r)[24]), "=r"((r)[25]), "=r"((r)[26]), "=r"((r)[27]), \
          "=r"((r)[28]), "=r"((r)[29]), "=r"((r)[30]), "=r"((r)[31]) \
        : "r"(tmem_addr))

// SW128 K-major SMEM descriptor (layout=SW128, Blackwell version=1, LBO=1, SBO=64)
static constexpr uint64_t SMEM_DESC_BASE_SW128 =
    (uint64_t(2) << 61) | (uint64_t(1) << 46) | (uint64_t(64) << 32) | (uint64_t(1) << 16);
#define MAKE_SMEM_DESC(base_addr) \
    (SMEM_DESC_BASE_SW128 | ((uint64_t)((base_addr) >> 4) & 0x3FFF))

// cg1 bf16 SS MMA: D[m,n] += sum_k A[m,k]*B[n,k]
__device__ __forceinline__ void mma_f16_ss(uint32_t d, uint64_t ad, uint64_t bd,
                                           uint32_t idesc, uint32_t acc) {
    asm volatile(
        "{\n\t.reg .pred p;\n\tsetp.ne.u32 p, %5, 0;\n\t"
        "tcgen05.mma.cta_group::1.kind::f16 [%0], %1, %2, %3, {%4, %4, %4, %4}, p;\n\t}"
        :: "r"(d), "l"(ad), "l"(bd), "r"(idesc), "r"(0u), "r"(acc) : "memory");
}
#endif  // TC_OK

// ---------------------------------------------------------------------------
// GEMM tile configuration
// ---------------------------------------------------------------------------
static constexpr int TILE_M   = 128;
static constexpr int TILE_N   = 512;   // TMEM D = 512 fp32 cols (2 MMAs of N=256)
static constexpr int TILE_K   = 64;    // one SW128 row = 64 bf16 = 128 B
static constexpr int N_TILES  = HID   / TILE_N;  // 4
static constexpr int K_CHUNKS = IN_SZ / TILE_K;  // 16

static constexpr uint32_t S_TMEM = 0;
static constexpr uint32_t S_BAR0 = 16;
static constexpr uint32_t S_BAR1 = 24;
static constexpr uint32_t S_DONE = 32;
static constexpr uint32_t S_B1   = 1024;
static constexpr uint32_t S_W2   = 1024 + 4 * HID;          // 9216
static constexpr uint32_t S_A    = S_W2 + 4 * HID;          // 17408 (1024-aligned)
static constexpr uint32_t A_STAGE_BYTES = TILE_M * 128;     // 16384
static constexpr uint32_t S_B    = S_A + 2 * A_STAGE_BYTES; // 50176 (1024-aligned)
static constexpr uint32_t B_STAGE_BYTES = TILE_N * 128;     // 65536
static constexpr uint32_t SMEM_BYTES = S_B + 2 * B_STAGE_BYTES; // 181248

// idesc: dtype=F32(bit4), atype=BF16(bit7), btype=BF16(bit10), N=256 (N/8 << 17), M=128 (M/16 << 24)
static constexpr uint32_t IDESC =
    (1u << 4) | (1u << 7) | (1u << 10) | ((256u / 8) << 17) | ((128u / 16) << 24);

// Per-chunk loads: each of 128 threads copies 8 A-chunks + 32 B-chunks of 16 B.
__device__ __forceinline__ void load_chunk(uint32_t sb, int s,
                                           const __nv_bfloat16* pA,
                                           const __nv_bfloat16* pB,
                                           uint32_t swz0) {
    uint32_t dA = sb + S_A + (uint32_t)s * A_STAGE_BYTES + swz0;
#pragma unroll
    for (int j = 0; j < 8; j++)                          // rows r0 + 16j  (0..127)
        cp16(dA + (uint32_t)j * 2048u, pA + (size_t)j * 16 * IN_SZ);
    uint32_t dB = sb + S_B + (uint32_t)s * B_STAGE_BYTES + swz0;
#pragma unroll
    for (int j = 0; j < 32; j++)                         // rows r0 + 16j  (0..511)
        cp16(dB + (uint32_t)j * 2048u, pB + (size_t)j * 16 * IN_SZ);
    cp_commit();
}

// ---------------------------------------------------------------------------
// Fused expert GEMM: per CTA = (expert e, 128 batch rows), full N=2048, K=1024
// Epilogue fuses bias + relu + dot(W2) -> z scalar per row.
// ---------------------------------------------------------------------------
__global__ void __launch_bounds__(128, 1)
gemm_fused(const float* __restrict__ b1, const float* __restrict__ W2) {
#if TC_OK
    extern __shared__ __align__(1024) uint8_t smem[];
    const uint32_t sb = smem_to_u32(smem);
    const int tid = threadIdx.x;
    const int wid = tid >> 5;
    const int e   = blockIdx.x >> 6;          // 64 row-blocks per expert
    const int m0  = (blockIdx.x & 63) * TILE_M;

    if (tid == 0) {
        MBARRIER_INIT(sb + S_BAR0, 1);
        MBARRIER_INIT(sb + S_BAR1, 1);
        MBARRIER_INIT(sb + S_DONE, 1);
    }
    if (wid == 0) {
        TCGEN05_ALLOC(sb + S_TMEM, 512);
        TCGEN05_RELINQUISH_ALLOC_PERMIT();
    }

    float* s_b1 = (float*)(smem + S_B1);
    float* s_w2 = (float*)(smem + S_W2);
    for (int i = tid; i < HID; i += 128) {
        s_b1[i] = __ldg(b1 + (size_t)e * HID + i);
        s_w2[i] = __ldg(W2 + (size_t)e * HID + i);
    }
    __syncthreads();

    uint32_t tmem;
    asm volatile("ld.shared.b32 %0, [%1];" : "=r"(tmem) : "r"(sb + S_TMEM));

    // per-thread cp.async geometry: thread t -> 16B column (t&7), base row (t>>3)
    const int c8 = (tid & 7) * 8;                     // bf16 elements
    const int r0 = tid >> 3;
    const uint32_t off0 = (uint32_t)(r0 * 128 + (tid & 7) * 16);
    const uint32_t swz0 = off0 ^ ((off0 >> 3) & 0x70);  // swizzle invariant in j (row step 16)
    const __nv_bfloat16* pA0 = g_xb  + (size_t)(m0 + r0) * IN_SZ + c8;
    const __nv_bfloat16* pB0 = g_w1b + ((size_t)e * HID + r0) * IN_SZ + c8;

    float zacc[4] = {0.f, 0.f, 0.f, 0.f};

    for (int nt = 0; nt < N_TILES; nt++) {
        const __nv_bfloat16* pBt = pB0 + (size_t)nt * TILE_N * IN_SZ;

        load_chunk(sb, 0, pA0, pBt, swz0);            // prologue: chunk 0 -> stage 0

        for (int kc = 0; kc < K_CHUNKS; kc++) {
            const int s = kc & 1;
            if (kc + 1 < K_CHUNKS) {
                const int s2 = s ^ 1;
                const int u = (kc + 1) >> 1;          // use index of stage s2 this tile
                if (u >= 1)                            // wait MMA drain of previous use
                    MBARRIER_WAIT_PARITY(sb + (s2 ? S_BAR1 : S_BAR0), (u - 1) & 1);
                load_chunk(sb, s2, pA0 + (kc + 1) * TILE_K, pBt + (kc + 1) * TILE_K, swz0);
                cp_wait_1();                           // chunk kc data resident
            } else {
                cp_wait_0();
            }
            FENCE_PROXY_ASYNC_SHARED_CTA();            // writer-side proxy fence
            __syncthreads();

            if (wid == 0 && elect_one_pred()) {
                TCGEN05_FENCE_AFTER();
                const uint64_t ad = MAKE_SMEM_DESC(sb + S_A + (uint32_t)s * A_STAGE_BYTES);
                const uint64_t bd = MAKE_SMEM_DESC(sb + S_B + (uint32_t)s * B_STAGE_BYTES);
#pragma unroll
                for (int nh = 0; nh < 2; nh++) {
#pragma unroll
                    for (int ks = 0; ks < 4; ks++) {   // 4 x K16 per 64-wide chunk
                        mma_f16_ss(tmem + nh * 256,
                                   ad + ks * 2,
                                   bd + (uint64_t)nh * 2048 + ks * 2,
                                   IDESC,
                                   (uint32_t)((kc | ks) != 0));
                    }
                }
                TCGEN05_COMMIT(sb + (s ? S_BAR1 : S_BAR0));
                if (kc == K_CHUNKS - 1) TCGEN05_COMMIT(sb + S_DONE);
            }
        }

        // ---- epilogue for this N-tile: D[128,512] -> relu(.+b1) . W2 ----
        MBARRIER_WAIT_PARITY(sb + S_DONE, nt & 1);
        TCGEN05_FENCE_AFTER();
        for (int ch = 0; ch < 16; ch++) {
            uint32_t dr[32];
            TCGEN05_LD_32X32B_X32(dr, tmem + ch * 32);
            TCGEN05_WAIT_LD();
            const int nb = nt * TILE_N + ch * 32;
#pragma unroll
            for (int c = 0; c < 32; c++) {
                float h = __uint_as_float(dr[c]) + s_b1[nb + c];
                h = fmaxf(h, 0.f);
                zacc[c & 3] = fmaf(h, s_w2[nb + c], zacc[c & 3]);
            }
        }
        TCGEN05_FENCE_BEFORE();
        __syncthreads();   // D fully consumed before next tile's MMAs overwrite it
    }

    const float z = (zacc[0] + zacc[1]) + (zacc[2] + zacc[3]);
    g_zbuf[(size_t)e * BATCH_SZ + m0 + tid] = z;

    __syncthreads();
    if (wid == 0) TCGEN05_DEALLOC(tmem, 512);
#endif  // TC_OK
}

// ---------------------------------------------------------------------------
// fp32 -> bf16 conversions
// ---------------------------------------------------------------------------
__global__ void cvt_x_kernel(const float4* __restrict__ x) {
    const size_t i = (size_t)blockIdx.x * blockDim.x + threadIdx.x;  // < B*I/4
    const float4 v = x[i];
    __nv_bfloat162* dst = reinterpret_cast<__nv_bfloat162*>(g_xb);
    dst[2 * i]     = __floats2bfloat162_rn(v.x, v.y);
    dst[2 * i + 1] = __floats2bfloat162_rn(v.z, v.w);
}

// W1 [E][K=1024][H=2048] fp32  ->  g_w1b [E][H][K] bf16 (tiled transpose)
__global__ void cvt_w1_kernel(const float* __restrict__ W1) {
    __shared__ float tile[32][33];
    const int e  = blockIdx.z;
    const int h0 = blockIdx.x * 32;
    const int k0 = blockIdx.y * 32;
    const float* src = W1 + (size_t)e * IN_SZ * HID;
#pragma unroll
    for (int j = 0; j < 4; j++) {
        const int k = k0 + threadIdx.y + j * 8;
        tile[threadIdx.y + j * 8][threadIdx.x] = src[(size_t)k * HID + h0 + threadIdx.x];
    }
    __syncthreads();
    __nv_bfloat16* dst = g_w1b + (size_t)e * HID * IN_SZ;
#pragma unroll
    for (int j = 0; j < 4; j++) {
        const int h = h0 + threadIdx.y + j * 8;
        dst[(size_t)h * IN_SZ + k0 + threadIdx.x] =
            __float2bfloat16(tile[threadIdx.x][threadIdx.y + j * 8]);
    }
}

// ---------------------------------------------------------------------------
// Final reduce: out[m] = mean_e sigmoid(z[e][m] + b2[e])
// ---------------------------------------------------------------------------
__global__ void reduce_kernel(const float* __restrict__ b2, float* __restrict__ out) {
    const int i = blockIdx.x * blockDim.x + threadIdx.x;  // < 8192
    float s = 0.f;
#pragma unroll
    for (int ex = 0; ex < N_EXPERTS; ex++) {
        const float z = g_zbuf[(size_t)ex * BATCH_SZ + i] + b2[ex];
        s += 1.f / (1.f + expf(-z));
    }
    out[i] = s * (1.f / N_EXPERTS);
}

// ---------------------------------------------------------------------------
// Harness entry
// ---------------------------------------------------------------------------
extern "C" void kernel_launch(void* const* d_in, const int* in_sizes, int n_in,
                              void* d_out, int out_size) {
    (void)in_sizes; (void)n_in; (void)out_size;
    const float* x  = (const float*)d_in[0];
    const float* W1 = (const float*)d_in[1];
    const float* b1 = (const float*)d_in[2];
    const float* W2 = (const float*)d_in[3];
    const float* b2 = (const float*)d_in[4];
    float* out = (float*)d_out;

    cudaFuncSetAttribute(gemm_fused, cudaFuncAttributeMaxDynamicSharedMemorySize,
                         (int)SMEM_BYTES);

    cvt_x_kernel<<<(BATCH_SZ * IN_SZ / 4) / 256, 256>>>((const float4*)x);

    dim3 tb(32, 8);
    dim3 tg(HID / 32, IN_SZ / 32, N_EXPERTS);
    cvt_w1_kernel<<<tg, tb>>>(W1);

    gemm_fused<<<N_EXPERTS * (BATCH_SZ / TILE_M), 128, SMEM_BYTES>>>(b1, W2);

    reduce_kernel<<<BATCH_SZ / 256, 256>>>(b2, out);
}

// round 3
// speedup vs baseline: 1.0462x; 1.0462x over previous
#include <cuda_runtime.h>
#include <cuda_bf16.h>
#include <cstdint>

// ---------------------------------------------------------------------------
// Arch gate: tcgen05 is sm_103a-ONLY. The harness also builds a plain
// compute_103 PTX phase; guard all tcgen05 code so that phase compiles.
// ---------------------------------------------------------------------------
#if defined(__CUDA_ARCH__) && (__CUDA_ARCH__ == 1030) && defined(__CUDA_ARCH_FEAT_SM103_ALL)
#define TC_OK 1
#else
#define TC_OK 0
#endif

// ---------------------------------------------------------------------------
// Problem constants
// ---------------------------------------------------------------------------
#define N_EXPERTS 30
#define IN_SZ     1024
#define HID       2048
#define BATCH_SZ  8192

// ---------------------------------------------------------------------------
// Device scratch
// ---------------------------------------------------------------------------
__device__ __align__(16) __nv_bfloat16 g_xb [(size_t)BATCH_SZ * IN_SZ];          // 16 MB
__device__ __align__(16) __nv_bfloat16 g_w1b[(size_t)N_EXPERTS * HID * IN_SZ];   // 126 MB, [E][H][K] K-major
__device__ float g_zbuf[(size_t)N_EXPERTS * BATCH_SZ];                            // 1 MB

// ---------------------------------------------------------------------------
// PTX helpers
// ---------------------------------------------------------------------------
__device__ __forceinline__ uint32_t smem_to_u32(const void* p) {
    uint32_t a;
    asm("{ .reg .u64 t; cvta.to.shared.u64 t, %1; cvt.u32.u64 %0, t; }"
        : "=r"(a) : "l"(p));
    return a;
}

__device__ __forceinline__ uint32_t elect_one_pred() {
    uint32_t pred;
    asm volatile(
        "{\n\t.reg .pred p;\n\telect.sync _|p, 0xFFFFFFFF;\n\tselp.b32 %0, 1, 0, p;\n\t}"
        : "=r"(pred));
    return pred;
}

__device__ __forceinline__ uint32_t cluster_rank() {
    uint32_t r;
    asm("mov.u32 %0, %%cluster_ctarank;" : "=r"(r));
    return r;
}

#define MBARRIER_INIT(addr, cnt) \
    asm volatile("mbarrier.init.shared.b64 [%0], %1;" :: "r"((uint32_t)(addr)), "r"((uint32_t)(cnt)) : "memory")

// local wait, acquire at cta scope
#define MBARRIER_WAIT_PARITY(mbar_smem_addr, phase_parity) do { \
    uint32_t _mbar = (uint32_t)(mbar_smem_addr); \
    uint32_t _parity = (uint32_t)(phase_parity); \
    uint32_t _done; \
    asm volatile( \
        "{\n\t.reg .pred p;\n\t" \
        "mbarrier.try_wait.parity.acquire.cta.shared::cta.b64 p, [%1], %2;\n\t" \
        "selp.b32 %0, 1, 0, p;\n\t}" \
        : "=r"(_done) : "r"(_mbar), "r"(_parity) : "memory"); \
    if (!_done) { \
        asm volatile( \
            "{\n\t.reg .pred P1;\n\t" \
            "WAIT_LOOP_%=:\n\t" \
            "mbarrier.try_wait.parity.acquire.cta.shared::cta.b64 P1, [%0], %1, 0x989680;\n\t" \
            "@P1 bra.uni WAIT_DONE_%=;\n\t" \
            "bra.uni WAIT_LOOP_%=;\n\t" \
            "WAIT_DONE_%=:\n\t}" \
            :: "r"(_mbar), "r"(_parity) : "memory"); \
    } \
} while (0)

// cluster-scope acquire wait (leader waiting on peer-produced data)
#define MBARRIER_WAIT_PARITY_CLU(mbar_smem_addr, phase_parity) do { \
    uint32_t _mbar = (uint32_t)(mbar_smem_addr); \
    uint32_t _parity = (uint32_t)(phase_parity); \
    uint32_t _done; \
    asm volatile( \
        "{\n\t.reg .pred p;\n\t" \
        "mbarrier.try_wait.parity.acquire.cluster.shared::cta.b64 p, [%1], %2;\n\t" \
        "selp.b32 %0, 1, 0, p;\n\t}" \
        : "=r"(_done) : "r"(_mbar), "r"(_parity) : "memory"); \
    if (!_done) { \
        asm volatile( \
            "{\n\t.reg .pred P1;\n\t" \
            "WAIT_LOOP_%=:\n\t" \
            "mbarrier.try_wait.parity.acquire.cluster.shared::cta.b64 P1, [%0], %1, 0x989680;\n\t" \
            "@P1 bra.uni WAIT_DONE_%=;\n\t" \
            "bra.uni WAIT_LOOP_%=;\n\t" \
            "WAIT_DONE_%=:\n\t}" \
            :: "r"(_mbar), "r"(_parity) : "memory"); \
    } \
} while (0)

// arrive on the same-offset mbarrier in cluster rank 0 (proven helper form)
#define MBARRIER_ARRIVE_RANK0(local_mbar_addr) \
    asm volatile( \
        "{\n\t.reg .b32 remAddr32;\n\t" \
        "mapa.shared::cluster.u32 remAddr32, %0, 0;\n\t" \
        "mbarrier.arrive.shared::cluster.b64 _, [remAddr32];\n\t}" \
        :: "r"((uint32_t)(local_mbar_addr)) : "memory")

#define CLUSTER_SYNC() do { \
    asm volatile("barrier.cluster.arrive.aligned;" ::: "memory"); \
    asm volatile("barrier.cluster.wait.aligned;" ::: "memory"); \
} while (0)

__device__ __forceinline__ void cp16(uint32_t dst_smem, const void* src_gmem) {
    asm volatile("cp.async.cg.shared.global [%0], [%1], 16;"
                 :: "r"(dst_smem), "l"(src_gmem) : "memory");
}
__device__ __forceinline__ void cp_commit() { asm volatile("cp.async.commit_group;" ::: "memory"); }
#define CP_WAIT_GROUP(n) asm volatile("cp.async.wait_group %0;" :: "n"(n) : "memory")
#define FENCE_PROXY_ASYNC_SHARED_CTA() asm volatile("fence.proxy.async.shared::cta;" ::: "memory")

#if TC_OK
#define TCGEN05_ALLOC_CG2(smem_result_addr, nCols) \
    asm volatile("tcgen05.alloc.cta_group::2.sync.aligned.shared::cta.b32 [%0], %1;" \
        :: "r"((uint32_t)(smem_result_addr)), "r"((uint32_t)(nCols)) : "memory")

#define TCGEN05_DEALLOC_CG2(tmem_addr, nCols) \
    asm volatile("tcgen05.dealloc.cta_group::2.sync.aligned.b32 %0, %1;" \
        :: "r"(tmem_addr), "r"((uint32_t)(nCols)))

#define TCGEN05_RELINQUISH_CG2() \
    asm volatile("tcgen05.relinquish_alloc_permit.cta_group::2.sync.aligned;")

#define TCGEN05_COMMIT_MC_CG2(mbar_smem_addr, cta_mask) \
    asm volatile("tcgen05.commit.cta_group::2.mbarrier::arrive::one.shared::cluster.multicast::cluster.b64 [%0], %1;" \
        :: "r"((uint32_t)(mbar_smem_addr)), "h"((uint16_t)(cta_mask)) : "memory")

#define TCGEN05_WAIT_LD()  asm volatile("tcgen05.wait::ld.sync.aligned;" ::: "memory")
#define TCGEN05_FENCE_BEFORE() asm volatile("tcgen05.fence::before_thread_sync;" ::: "memory")
#define TCGEN05_FENCE_AFTER()  asm volatile("tcgen05.fence::after_thread_sync;" ::: "memory")

#define TCGEN05_LD_32X32B_X32(r, tmem_addr) \
    asm volatile( \
        "tcgen05.ld.sync.aligned.32x32b.x32.b32 " \
        "{%0, %1, %2, %3, %4, %5, %6, %7, " \
        " %8, %9, %10, %11, %12, %13, %14, %15, " \
        " %16, %17, %18, %19, %20, %21, %22, %23, " \
        " %24, %25, %26, %27, %28, %29, %30, %31}, [%32];" \
        : "=r"((r)[0]),  "=r"((r)[1]),  "=r"((r)[2]),  "=r"((r)[3]), \
          "=r"((r)[4]),  "=r"((r)[5]),  "=r"((r)[6]),  "=r"((r)[7]), \
          "=r"((r)[8]),  "=r"((r)[9]),  "=r"((r)[10]), "=r"((r)[11]), \
          "=r"((r)[12]), "=r"((r)[13]), "=r"((r)[14]), "=r"((r)[15]), \
          "=r"((r)[16]), "=r"((r)[17]), "=r"((r)[18]), "=r"((r)[19]), \
          "=r"((r)[20]), "=r"((r)[21]), "=r"((r)[22]), "=r"((r)[23]), \
          "=r"((r)[24]), "=r"((r)[25]), "=r"((r)[26]), "=r"((r)[27]), \
          "=r"((r)[28]), "=r"((r)[29]), "=r"((r)[30]), "=r"((r)[31]) \
        : "r"(tmem_addr))

// SW128 K-major SMEM descriptor (layout=SW128, Blackwell version=1, LBO=1, SBO=64)
static constexpr uint64_t SMEM_DESC_BASE_SW128 =
    (uint64_t(2) << 61) | (uint64_t(1) << 46) | (uint64_t(64) << 32) | (uint64_t(1) << 16);
#define MAKE_SMEM_DESC(base_addr) \
    (SMEM_DESC_BASE_SW128 | ((uint64_t)((base_addr) >> 4) & 0x3FFF))

// cg2 bf16 SS MMA: D[256,N] += A[256,k16] * B[N,k16]^T  (M split 128/128, B split N/2 per CTA)
__device__ __forceinline__ void mma_f16_ss_cg2(uint32_t d, uint64_t ad, uint64_t bd,
                                               uint32_t idesc, uint32_t acc) {
    asm volatile(
        "{\n\t.reg .pred p;\n\tsetp.ne.u32 p, %5, 0;\n\t"
        "tcgen05.mma.cta_group::2.kind::f16 [%0], %1, %2, %3, "
        "{%4, %4, %4, %4, %4, %4, %4, %4}, p;\n\t}"
        :: "r"(d), "l"(ad), "l"(bd), "r"(idesc), "r"(0u), "r"(acc) : "memory");
}
#endif  // TC_OK

// ---------------------------------------------------------------------------
// Tile configuration: CTA-pair computes 256 rows x full HID; per K-chunk = 64.
// ---------------------------------------------------------------------------
static constexpr int TILE_N    = 512;            // per TMEM pass (2 MMAs of N=256)
static constexpr int TILE_K    = 64;             // one SW128 row = 64 bf16 = 128 B
static constexpr int N_TILES   = HID / TILE_N;   // 4
static constexpr int KC_TILE   = IN_SZ / TILE_K; // 16 chunks per N-tile
static constexpr int KK_TOT    = N_TILES * KC_TILE;  // 64
static constexpr int STAGES    = 3;

static constexpr uint32_t S_TMEM  = 0;
static constexpr uint32_t S_FULL  = 16;                  // 3 x 8B (leader-side counts)
static constexpr uint32_t S_EMPTY = 40;                  // 3 x 8B
static constexpr uint32_t S_DONE  = 64;
static constexpr uint32_t S_EDONE = 72;
static constexpr uint32_t S_B1    = 1024;
static constexpr uint32_t S_W2    = 1024 + 4 * HID;          // 9216
static constexpr uint32_t S_A     = S_W2 + 4 * HID;          // 17408 (1024-aligned)
static constexpr uint32_t A_STAGE_BYTES = 128 * 128;         // 16384
static constexpr uint32_t S_B     = S_A + STAGES * A_STAGE_BYTES;  // 66560
static constexpr uint32_t B_STAGE_BYTES = 256 * 128;         // 32768 (256 B-rows per CTA)
static constexpr uint32_t SMEM_BYTES = S_B + STAGES * B_STAGE_BYTES; // 164864

// idesc: dtype=F32(bit4), atype=BF16(bit7), btype=BF16(bit10), N=256, M=256
static constexpr uint32_t IDESC =
    (1u << 4) | (1u << 7) | (1u << 10) | ((256u / 8) << 17) | ((256u / 16) << 24);

// ---------------------------------------------------------------------------
// Fused expert GEMM, cg2. Pair = 2 CTAs: rows m0p..m0p+255 of one expert.
// ---------------------------------------------------------------------------
__global__ void __launch_bounds__(128, 1) __cluster_dims__(2, 1, 1)
gemm_fused(const float* __restrict__ b1, const float* __restrict__ W2) {
#if TC_OK
    extern __shared__ __align__(1024) uint8_t smem[];
    const uint32_t sb = smem_to_u32(smem);
    const int tid  = threadIdx.x;
    const int wid  = tid >> 5;
    const uint32_t rank = cluster_rank();
    const int pair = blockIdx.x >> 1;
    const int e    = pair >> 5;                  // 32 pairs per expert
    const int m0p  = (pair & 31) * 256;          // pair row base
    const int m0   = m0p + (int)rank * 128;      // this CTA's 128 rows

    if (wid == 0) TCGEN05_ALLOC_CG2(sb + S_TMEM, 512);
    if (tid == 0) {
        if (rank == 0) {
            for (int s = 0; s < STAGES; s++) MBARRIER_INIT(sb + S_FULL + 8 * s, 2);
            MBARRIER_INIT(sb + S_EDONE, 2);
        }
        for (int s = 0; s < STAGES; s++) MBARRIER_INIT(sb + S_EMPTY + 8 * s, 1);
        MBARRIER_INIT(sb + S_DONE, 1);
    }
    __syncthreads();

    uint32_t tmem;
    asm volatile("ld.shared.b32 %0, [%1];" : "=r"(tmem) : "r"(sb + S_TMEM));

    float* s_b1 = (float*)(smem + S_B1);
    float* s_w2 = (float*)(smem + S_W2);
    for (int i = tid; i < HID; i += 128) {
        s_b1[i] = __ldg(b1 + (size_t)e * HID + i);
        s_w2[i] = __ldg(W2 + (size_t)e * HID + i);
    }
    __syncthreads();
    CLUSTER_SYNC();   // barriers initialized cluster-wide before any arrivals

    // per-thread cp.async geometry: thread t -> 16B column (t&7), base row (t>>3)
    const int c8 = (tid & 7) * 8;                       // bf16 elements
    const int r0 = tid >> 3;                            // 0..15
    const uint32_t off0 = (uint32_t)(r0 * 128 + (tid & 7) * 16);
    const uint32_t swz0 = off0 ^ ((off0 >> 3) & 0x70);  // swizzle invariant under +j*2048
    const __nv_bfloat16* pA0 = g_xb + (size_t)(m0 + r0) * IN_SZ + c8;
    // B rows for this CTA: hid = nt*512 + nh*256 + rank*128 + (local row & 127)
    const __nv_bfloat16* pB0 = g_w1b + ((size_t)e * HID + (size_t)rank * 128 + r0) * IN_SZ + c8;

    const bool leader = (rank == 0) && (wid == 0) && elect_one_pred();
    float zacc[4] = {0.f, 0.f, 0.f, 0.f};

    // producer: load chunk 'la' into stage la % STAGES
    auto load_chunk = [&](int la) {
        const int s     = la % STAGES;
        const int nt_la = la >> 4;
        const int kc_la = la & 15;
        const __nv_bfloat16* pA = pA0 + kc_la * TILE_K;
        uint32_t dA = sb + S_A + (uint32_t)s * A_STAGE_BYTES + swz0;
#pragma unroll
        for (int j = 0; j < 8; j++)                       // A rows r0+16j (0..127)
            cp16(dA + (uint32_t)j * 2048u, pA + (size_t)j * 16 * IN_SZ);
        const __nv_bfloat16* pB = pB0 + ((size_t)nt_la * 512) * IN_SZ + kc_la * TILE_K;
        uint32_t dB = sb + S_B + (uint32_t)s * B_STAGE_BYTES + swz0;
#pragma unroll
        for (int j = 0; j < 16; j++) {                    // B local rows r0+16j (0..255)
            const size_t grow = (size_t)((j >> 3) * 256 + (j & 7) * 16) * IN_SZ;
            cp16(dB + (uint32_t)j * 2048u, pB + grow);
        }
        cp_commit();
    };

    // prologue: chunks 0, 1 -> stages 0, 1
    load_chunk(0);
    load_chunk(1);

    for (int kk = 0; kk < KK_TOT; kk++) {
        const int s  = kk % STAGES;
        const int nt = kk >> 4;
        const int kc = kk & 15;

        // ---- producer: stage for chunk la = kk+2 ----
        const int la = kk + STAGES - 1;
        if (la < KK_TOT) {
            const int sla = la % STAGES;
            const int ula = la / STAGES;
            if (ula >= 1)   // wait MMA drain of this stage's previous use
                MBARRIER_WAIT_PARITY(sb + S_EMPTY + 8 * sla, (ula - 1) & 1);
            load_chunk(la);
            CP_WAIT_GROUP(STAGES - 1);     // chunk kk fully resident
        } else {
            CP_WAIT_GROUP(0);
        }
        FENCE_PROXY_ASYNC_SHARED_CTA();
        __syncthreads();
        if (tid == 0) MBARRIER_ARRIVE_RANK0(sb + S_FULL + 8 * s);

        // ---- leader: issue MMAs for chunk kk ----
        if (leader) {
            if (kc == 0 && nt >= 1)        // both epilogues done -> D reusable
                MBARRIER_WAIT_PARITY(sb + S_EDONE, (nt - 1) & 1);
            MBARRIER_WAIT_PARITY_CLU(sb + S_FULL + 8 * s, (kk / STAGES) & 1);
            TCGEN05_FENCE_AFTER();
            const uint64_t ad = MAKE_SMEM_DESC(sb + S_A + (uint32_t)s * A_STAGE_BYTES);
#pragma unroll
            for (int nh = 0; nh < 2; nh++) {
                const uint64_t bd = MAKE_SMEM_DESC(sb + S_B + (uint32_t)s * B_STAGE_BYTES
                                                   + (uint32_t)nh * 16384u);
#pragma unroll
                for (int ks = 0; ks < 4; ks++)
                    mma_f16_ss_cg2(tmem + nh * 256, ad + ks * 2, bd + ks * 2,
                                   IDESC, (uint32_t)((kc | ks) != 0));
            }
            TCGEN05_COMMIT_MC_CG2(sb + S_EMPTY + 8 * s, 0x3);
            if (kc == KC_TILE - 1) TCGEN05_COMMIT_MC_CG2(sb + S_DONE, 0x3);
        }

        // ---- epilogue at end of each N-tile ----
        if (kc == KC_TILE - 1) {
            MBARRIER_WAIT_PARITY(sb + S_DONE, nt & 1);
            TCGEN05_FENCE_AFTER();
            for (int ch = 0; ch < 16; ch++) {
                uint32_t dr[32];
                TCGEN05_LD_32X32B_X32(dr, tmem + ch * 32);
                TCGEN05_WAIT_LD();
                const int nb = nt * TILE_N + ch * 32;
#pragma unroll
                for (int c = 0; c < 32; c++) {
                    float h = __uint_as_float(dr[c]) + s_b1[nb + c];
                    h = fmaxf(h, 0.f);
                    zacc[c & 3] = fmaf(h, s_w2[nb + c], zacc[c & 3]);
                }
            }
            TCGEN05_FENCE_BEFORE();
            __syncthreads();               // whole CTA consumed D
            if (tid == 0) MBARRIER_ARRIVE_RANK0(sb + S_EDONE);
        }
    }

    const float z = (zacc[0] + zacc[1]) + (zacc[2] + zacc[3]);
    g_zbuf[(size_t)e * BATCH_SZ + m0 + tid] = z;

    __syncthreads();
    if (wid == 0) {
        TCGEN05_RELINQUISH_CG2();
        TCGEN05_DEALLOC_CG2(tmem, 512);
    }
    CLUSTER_SYNC();   // peer may still have MMA/multicast targeting our SMEM
#endif  // TC_OK
}

// ---------------------------------------------------------------------------
// fp32 -> bf16 conversions
// ---------------------------------------------------------------------------
__global__ void cvt_x_kernel(const float4* __restrict__ x) {
    const size_t i = (size_t)blockIdx.x * blockDim.x + threadIdx.x;  // < B*I/4
    const float4 v = x[i];
    __nv_bfloat162* dst = reinterpret_cast<__nv_bfloat162*>(g_xb);
    dst[2 * i]     = __floats2bfloat162_rn(v.x, v.y);
    dst[2 * i + 1] = __floats2bfloat162_rn(v.z, v.w);
}

// W1 [E][K=1024][H=2048] fp32  ->  g_w1b [E][H][K] bf16 (tiled transpose)
__global__ void cvt_w1_kernel(const float* __restrict__ W1) {
    __shared__ float tile[32][33];
    const int e  = blockIdx.z;
    const int h0 = blockIdx.x * 32;
    const int k0 = blockIdx.y * 32;
    const float* src = W1 + (size_t)e * IN_SZ * HID;
#pragma unroll
    for (int j = 0; j < 4; j++) {
        const int k = k0 + threadIdx.y + j * 8;
        tile[threadIdx.y + j * 8][threadIdx.x] = src[(size_t)k * HID + h0 + threadIdx.x];
    }
    __syncthreads();
    __nv_bfloat16* dst = g_w1b + (size_t)e * HID * IN_SZ;
#pragma unroll
    for (int j = 0; j < 4; j++) {
        const int h = h0 + threadIdx.y + j * 8;
        dst[(size_t)h * IN_SZ + k0 + threadIdx.x] =
            __float2bfloat16(tile[threadIdx.x][threadIdx.y + j * 8]);
    }
}

// ---------------------------------------------------------------------------
// Final reduce: out[m] = mean_e sigmoid(z[e][m] + b2[e])
// ---------------------------------------------------------------------------
__global__ void reduce_kernel(const float* __restrict__ b2, float* __restrict__ out) {
    const int i = blockIdx.x * blockDim.x + threadIdx.x;  // < 8192
    float s = 0.f;
#pragma unroll
    for (int ex = 0; ex < N_EXPERTS; ex++) {
        const float z = g_zbuf[(size_t)ex * BATCH_SZ + i] + b2[ex];
        s += 1.f / (1.f + __expf(-z));
    }
    out[i] = s * (1.f / N_EXPERTS);
}

// ---------------------------------------------------------------------------
// Harness entry
// ---------------------------------------------------------------------------
extern "C" void kernel_launch(void* const* d_in, const int* in_sizes, int n_in,
                              void* d_out, int out_size) {
    (void)in_sizes; (void)n_in; (void)out_size;
    const float* x  = (const float*)d_in[0];
    const float* W1 = (const float*)d_in[1];
    const float* b1 = (const float*)d_in[2];
    const float* W2 = (const float*)d_in[3];
    const float* b2 = (const float*)d_in[4];
    float* out = (float*)d_out;

    cudaFuncSetAttribute(gemm_fused, cudaFuncAttributeMaxDynamicSharedMemorySize,
                         (int)SMEM_BYTES);

    cvt_x_kernel<<<(BATCH_SZ * IN_SZ / 4) / 256, 256>>>((const float4*)x);

    dim3 tb(32, 8);
    dim3 tg(HID / 32, IN_SZ / 32, N_EXPERTS);
    cvt_w1_kernel<<<tg, tb>>>(W1);

    // 1920 CTAs = 960 cluster pairs (cluster dims (2,1,1) via attribute)
    gemm_fused<<<N_EXPERTS * (BATCH_SZ / 256) * 2, 128, SMEM_BYTES>>>(b1, W2);

    reduce_kernel<<<BATCH_SZ / 256, 256>>>(b2, out);
}